// round 16
// baseline (speedup 1.0000x reference)
#include <cuda_runtime.h>

// SpringMass: B=4096 independent 2-state linear ODEs, T=4096 RK4 steps each.
// Affine scan over time (pass1 compose / pass2 scan / pass3 replay).
//
// R16: single scan per row. 256-thread CTA, 16 steps/thread, one block-wide
// scan over the whole row (vs 2 half-scans in R15: -43% instructions).
// Row staged once into 4 x 8KB swizzled quarter buffers; warp w touches only
// quarter w>>1 in pass1/pass3; output written in place and drained coalesced.
// 33KB smem x 6 CTAs = 48 warps/SM under launch_bounds(256,6).

#define T_LEN   4096
#define NTHR    256
#define QF4     512               // float4 per quarter (1024 steps)

namespace sm_consts {
constexpr double Cd = 0.1, dd = 0.01;
// A = alpha(k)*I + beta(k)*B, B=[[-C,-k],[1,0]] (deg-4 Taylor of exp(dt B))
constexpr double AL1d = -dd*dd/2.0 + Cd*dd*dd*dd/6.0 - Cd*Cd*dd*dd*dd*dd/24.0;
constexpr double AL2d = dd*dd*dd*dd/24.0;
constexpr double BE0d = dd - Cd*dd*dd/2.0 + Cd*Cd*dd*dd*dd/6.0 - Cd*Cd*Cd*dd*dd*dd*dd/24.0;
constexpr double BE1d = -dd*dd*dd/6.0 + Cd*dd*dd*dd*dd/12.0;
// forcing: g = c0*e1 + c1*B*e1, B*e1 = (-C,1)
constexpr double C00 = dd;
constexpr double C01 = dd*(-dd*dd/6.0 + dd*dd*dd*Cd/24.0);
constexpr double C10 = dd*(dd/2.0 - dd*dd*Cd/6.0 + dd*dd*dd*Cd*Cd/24.0);
constexpr double C11 = dd*(-dd*dd*dd/24.0);

constexpr float AL1 = (float)AL1d;
constexpr float AL2 = (float)AL2d;
constexpr float BE0 = (float)BE0d;
constexpr float BE1 = (float)BE1d;
constexpr float KG10 = (float)(C00 - Cd*C10);   // g1 = KG10 + KG11*k
constexpr float KG11 = (float)(C01 - Cd*C11);
constexpr float KG20 = (float)C10;              // g2 = KG20 + KG21*k
constexpr float KG21 = (float)C11;
constexpr float CF   = 0.1f;
}  // namespace sm_consts

struct Aff { float a11, a12, a21, a22, b1, b2; };

__device__ __forceinline__ Aff compose(const Aff& n, const Aff& o) {
    Aff r;
    r.a11 = fmaf(n.a11, o.a11, n.a12 * o.a21);
    r.a12 = fmaf(n.a11, o.a12, n.a12 * o.a22);
    r.a21 = fmaf(n.a21, o.a11, n.a22 * o.a21);
    r.a22 = fmaf(n.a21, o.a12, n.a22 * o.a22);
    r.b1  = fmaf(n.a11, o.b1, fmaf(n.a12, o.b2, n.b1));
    r.b2  = fmaf(n.a21, o.b1, fmaf(n.a22, o.b2, n.b2));
    return r;
}

// apply affine map to state: s' = A s + b   (4 FMA)
__device__ __forceinline__ void apply(const Aff& m, float& v, float& x) {
    float vn = fmaf(m.a11, v, fmaf(m.a12, x, m.b1));
    float xn = fmaf(m.a21, v, fmaf(m.a22, x, m.b2));
    v = vn; x = xn;
}

__device__ __forceinline__ Aff step_map(float k, float F) {
    using namespace sm_consts;
    Aff s;
    float al = fmaf(fmaf(AL2, k, AL1), k, 1.0f);
    float be = fmaf(BE1, k, BE0);
    s.a11 = fmaf(-CF, be, al);
    s.a12 = -k * be;
    s.a21 = be;
    s.a22 = al;
    s.b1 = F * fmaf(KG11, k, KG10);
    s.b2 = F * fmaf(KG21, k, KG20);
    return s;
}

// advance state, return xddot for this step (computed from NEW state)
__device__ __forceinline__ float step_state(float k, float F, float& v, float& x) {
    using namespace sm_consts;
    float al = fmaf(fmaf(AL2, k, AL1), k, 1.0f);
    float be = fmaf(BE1, k, BE0);
    float A11 = fmaf(-CF, be, al);
    float A12 = -k * be;
    float g1  = fmaf(KG11, k, KG10);
    float g2  = fmaf(KG21, k, KG20);
    float vn = fmaf(A11, v, fmaf(A12, x, F * g1));
    float xn = fmaf(be,  v, fmaf(al,  x, F * g2));
    v = vn; x = xn;
    return fmaf(-k, xn, fmaf(-CF, vn, F));
}

__device__ __forceinline__ Aff shfl_up_aff(const Aff& m, int off) {
    Aff r;
    r.a11 = __shfl_up_sync(0xffffffffu, m.a11, off);
    r.a12 = __shfl_up_sync(0xffffffffu, m.a12, off);
    r.a21 = __shfl_up_sync(0xffffffffu, m.a21, off);
    r.a22 = __shfl_up_sync(0xffffffffu, m.a22, off);
    r.b1  = __shfl_up_sync(0xffffffffu, m.b1,  off);
    r.b2  = __shfl_up_sync(0xffffffffu, m.b2,  off);
    return r;
}

// XOR swizzle for a quarter buffer: chunk cl (0..63) x float4 offset o (0..7).
// F bijective on the 3 low chunk bits, flips bit2 between adjacent chunks:
// conflict-free for staging, same-o chunk reads, in-place writes, drain.
__device__ __forceinline__ int Fsw(int c) {
    return ((c & 1) << 2) | ((c >> 1) & 3);
}
__device__ __forceinline__ int slot(int cl, int o) {
    return (cl << 3) | (o ^ Fsw(cl));
}

__device__ __forceinline__ void cp16(float4* smem_dst, const float4* gsrc) {
    unsigned s = (unsigned)__cvta_generic_to_shared(smem_dst);
    asm volatile("cp.async.cg.shared.global [%0], [%1], 16;" :: "r"(s), "l"(gsrc));
}
__device__ __forceinline__ void cp_commit() {
    asm volatile("cp.async.commit_group;" ::: "memory");
}
template <int N>
__device__ __forceinline__ void cp_wait() {
    asm volatile("cp.async.wait_group %0;" :: "n"(N) : "memory");
}

__global__ void __launch_bounds__(NTHR, 6)
spring_scan_kernel(const float* __restrict__ in,
                   const float* __restrict__ vinit,
                   const float* __restrict__ xinit,
                   float* __restrict__ out) {
    __shared__ float4 ring[4][QF4];        // 4 x 8KB quarter buffers (full row)
    __shared__ Aff wsum[NTHR / 32];

    const int b = blockIdx.x;
    const int l = threadIdx.x;
    const int lane = l & 31;
    const int w = l >> 5;

    const float4* gin  = reinterpret_cast<const float4*>(in + (long)b * T_LEN * 2);
    float4*       gout = reinterpret_cast<float4*>(out + (long)b * T_LEN);

    // ---- Stage the whole row: 4 quarters, coalesced cp.async ----
#pragma unroll
    for (int q = 0; q < 4; q++) {
#pragma unroll
        for (int r = 0; r < 2; r++) {
            int idx = r * NTHR + l;        // 0..511 within quarter
            cp16(&ring[q][slot(idx >> 3, idx & 7)], &gin[q * QF4 + idx]);
        }
        cp_commit();
    }
    cp_wait<0>();
    __syncthreads();

    const int cl   = l & 63;               // chunk within my quarter
    const int base = cl << 3;
    const int f    = Fsw(cl);
    float4* mybuf  = ring[l >> 6];         // uniform per warp (w>>1)

    // ---- Pass 1: compose this thread's 16-step chunk map ----
    float4 d0 = mybuf[base | (0 ^ f)];
    Aff M = step_map(d0.x, d0.y);          // identity compose peeled
    M = compose(step_map(d0.z, d0.w), M);
#pragma unroll
    for (int o = 1; o < 8; o++) {
        float4 d = mybuf[base | (o ^ f)];
        M = compose(step_map(d.x, d.y), M);
        M = compose(step_map(d.z, d.w), M);
    }

    // ---- Pass 2: warp scan of chunk maps ----
#pragma unroll
    for (int off = 1; off < 32; off <<= 1) {
        Aff o = shfl_up_aff(M, off);
        if (lane >= off) M = compose(M, o);
    }

    if (lane == 31) wsum[w] = M;
    __syncthreads();

    // ---- Cross-warp: run the initial STATE through warp-sum maps ----
    float sv = vinit[b], sx = xinit[b];    // running state
    float pv = sv, px = sx;                // state entering this warp
#pragma unroll
    for (int j = 0; j < NTHR / 32; j++) {
        if (j == w) { pv = sv; px = sx; }
        apply(wsum[j], sv, sx);
    }

    // ---- Chunk-entry state via STATE shuffle ----
    float zv = pv, zx = px;
    apply(M, zv, zx);                      // state after MY chunk
    float uv = __shfl_up_sync(0xffffffffu, zv, 1);
    float ux = __shfl_up_sync(0xffffffffu, zx, 1);
    float v = (lane == 0) ? pv : uv;
    float x = (lane == 0) ? px : ux;

    // ---- Pass 3: replay 16 steps, write xddot in place ----
    // Output f4 j consumes input f4 2j,2j+1 (j <= 2j: already consumed).
#pragma unroll
    for (int j = 0; j < 4; j++) {
        float4 e0 = mybuf[base | ((2 * j) ^ f)];
        float4 e1 = mybuf[base | ((2 * j + 1) ^ f)];
        float4 o4;
        o4.x = step_state(e0.x, e0.y, v, x);
        o4.y = step_state(e0.z, e0.w, v, x);
        o4.z = step_state(e1.x, e1.y, v, x);
        o4.w = step_state(e1.z, e1.w, v, x);
        mybuf[base | (j ^ f)] = o4;
    }
    __syncthreads();                       // pass3 writes visible to drain

    // ---- Drain: swizzled smem -> coalesced global store ----
#pragma unroll
    for (int r = 0; r < 4; r++) {
        int idx = r * NTHR + l;            // output f4 index in row (0..1023)
        int c = idx >> 2;                  // owning chunk; c>>6 uniform per warp
        gout[idx] = ring[c >> 6][slot(c & 63, idx & 3)];
    }
}

extern "C" void kernel_launch(void* const* d_in, const int* in_sizes, int n_in,
                              void* d_out, int out_size) {
    const float* in = (const float*)d_in[0];       // (B, T, 2) float32
    const float* vi = (const float*)d_in[1];       // (B, 1)
    const float* xi = (const float*)d_in[2];       // (B, 1)
    float* out = (float*)d_out;                    // (B, T, 1) float32
    const int B = in_sizes[1];                     // 4096
    spring_scan_kernel<<<B, NTHR>>>(in, vi, xi, out);
}

// round 17
// speedup vs baseline: 1.0437x; 1.0437x over previous
#include <cuda_runtime.h>

// SpringMass: B=4096 independent 2-state linear ODEs, T=4096 RK4 steps each.
// Affine scan over time (pass1 compose / pass2 scan / pass3 replay).
//
// R17 = R15 (ring of three 8KB quarter buffers, 2 half-scans/row, 16-step
// chunks) + WARP-AUTONOMOUS staging: each warp cp.asyncs only its own 4KB
// region (cp.async wait_group is per-thread, so wait_group + __syncwarp
// suffices before pass1 -- no block barrier between stage and compute).
// Warps 0-1 prefetch their half-1 region (Q2) in the prologue; warps 2-3
// stage Q3 after the half-0 drain. Drain uses __stcs streaming stores.
// R16 (256-thr single scan) reverted: per-row scan work was unchanged and
// the staging pipeline was lost.

#define T_LEN   4096
#define NTHR    128
#define QF4     512               // float4 per quarter (1024 steps)
#define HO4     512               // output float4 per half (2048 steps)

namespace sm_consts {
constexpr double Cd = 0.1, dd = 0.01;
// A = alpha(k)*I + beta(k)*B, B=[[-C,-k],[1,0]] (deg-4 Taylor of exp(dt B))
constexpr double AL1d = -dd*dd/2.0 + Cd*dd*dd*dd/6.0 - Cd*Cd*dd*dd*dd*dd/24.0;
constexpr double AL2d = dd*dd*dd*dd/24.0;
constexpr double BE0d = dd - Cd*dd*dd/2.0 + Cd*Cd*dd*dd*dd/6.0 - Cd*Cd*Cd*dd*dd*dd*dd/24.0;
constexpr double BE1d = -dd*dd*dd/6.0 + Cd*dd*dd*dd*dd/12.0;
// forcing: g = c0*e1 + c1*B*e1, B*e1 = (-C,1)
constexpr double C00 = dd;
constexpr double C01 = dd*(-dd*dd/6.0 + dd*dd*dd*Cd/24.0);
constexpr double C10 = dd*(dd/2.0 - dd*dd*Cd/6.0 + dd*dd*dd*Cd*Cd/24.0);
constexpr double C11 = dd*(-dd*dd*dd/24.0);

constexpr float AL1 = (float)AL1d;
constexpr float AL2 = (float)AL2d;
constexpr float BE0 = (float)BE0d;
constexpr float BE1 = (float)BE1d;
constexpr float KG10 = (float)(C00 - Cd*C10);   // g1 = KG10 + KG11*k
constexpr float KG11 = (float)(C01 - Cd*C11);
constexpr float KG20 = (float)C10;              // g2 = KG20 + KG21*k
constexpr float KG21 = (float)C11;
constexpr float CF   = 0.1f;
}  // namespace sm_consts

struct Aff { float a11, a12, a21, a22, b1, b2; };

__device__ __forceinline__ Aff compose(const Aff& n, const Aff& o) {
    Aff r;
    r.a11 = fmaf(n.a11, o.a11, n.a12 * o.a21);
    r.a12 = fmaf(n.a11, o.a12, n.a12 * o.a22);
    r.a21 = fmaf(n.a21, o.a11, n.a22 * o.a21);
    r.a22 = fmaf(n.a21, o.a12, n.a22 * o.a22);
    r.b1  = fmaf(n.a11, o.b1, fmaf(n.a12, o.b2, n.b1));
    r.b2  = fmaf(n.a21, o.b1, fmaf(n.a22, o.b2, n.b2));
    return r;
}

// apply affine map to state: s' = A s + b   (4 FMA)
__device__ __forceinline__ void apply(const Aff& m, float& v, float& x) {
    float vn = fmaf(m.a11, v, fmaf(m.a12, x, m.b1));
    float xn = fmaf(m.a21, v, fmaf(m.a22, x, m.b2));
    v = vn; x = xn;
}

__device__ __forceinline__ Aff step_map(float k, float F) {
    using namespace sm_consts;
    Aff s;
    float al = fmaf(fmaf(AL2, k, AL1), k, 1.0f);
    float be = fmaf(BE1, k, BE0);
    s.a11 = fmaf(-CF, be, al);
    s.a12 = -k * be;
    s.a21 = be;
    s.a22 = al;
    s.b1 = F * fmaf(KG11, k, KG10);
    s.b2 = F * fmaf(KG21, k, KG20);
    return s;
}

// advance state, return xddot for this step (computed from NEW state)
__device__ __forceinline__ float step_state(float k, float F, float& v, float& x) {
    using namespace sm_consts;
    float al = fmaf(fmaf(AL2, k, AL1), k, 1.0f);
    float be = fmaf(BE1, k, BE0);
    float A11 = fmaf(-CF, be, al);
    float A12 = -k * be;
    float g1  = fmaf(KG11, k, KG10);
    float g2  = fmaf(KG21, k, KG20);
    float vn = fmaf(A11, v, fmaf(A12, x, F * g1));
    float xn = fmaf(be,  v, fmaf(al,  x, F * g2));
    v = vn; x = xn;
    return fmaf(-k, xn, fmaf(-CF, vn, F));
}

__device__ __forceinline__ Aff shfl_up_aff(const Aff& m, int off) {
    Aff r;
    r.a11 = __shfl_up_sync(0xffffffffu, m.a11, off);
    r.a12 = __shfl_up_sync(0xffffffffu, m.a12, off);
    r.a21 = __shfl_up_sync(0xffffffffu, m.a21, off);
    r.a22 = __shfl_up_sync(0xffffffffu, m.a22, off);
    r.b1  = __shfl_up_sync(0xffffffffu, m.b1,  off);
    r.b2  = __shfl_up_sync(0xffffffffu, m.b2,  off);
    return r;
}

// XOR swizzle for a quarter buffer: chunk cl (0..63) x float4 offset o (0..7).
// F bijective on the 3 low chunk bits, flips bit2 between adjacent chunks:
// conflict-free for staging, same-o chunk reads, in-place writes, drain.
__device__ __forceinline__ int Fsw(int c) {
    return ((c & 1) << 2) | ((c >> 1) & 3);
}
__device__ __forceinline__ int slot(int cl, int o) {
    return (cl << 3) | (o ^ Fsw(cl));
}

__device__ __forceinline__ void cp16(float4* smem_dst, const float4* gsrc) {
    unsigned s = (unsigned)__cvta_generic_to_shared(smem_dst);
    asm volatile("cp.async.cg.shared.global [%0], [%1], 16;" :: "r"(s), "l"(gsrc));
}
__device__ __forceinline__ void cp_commit() {
    asm volatile("cp.async.commit_group;" ::: "memory");
}
template <int N>
__device__ __forceinline__ void cp_wait() {
    asm volatile("cp.async.wait_group %0;" :: "n"(N) : "memory");
}

// Warp-local stage: this warp copies its own 256-float4 (4KB) region
// (chunks rc..rc+31 of buffer qb) from gsrc_region, then commits a group.
__device__ __forceinline__ void stage_region(float4* qb, const float4* gsrc_region,
                                             int rc, int lane) {
#pragma unroll
    for (int r = 0; r < 8; r++) {
        int idx = r * 32 + lane;                 // 0..255 within region
        cp16(&qb[slot(rc + (idx >> 3), idx & 7)], &gsrc_region[idx]);
    }
    cp_commit();
}

__global__ void __launch_bounds__(NTHR, 9)
spring_scan_kernel(const float* __restrict__ in,
                   const float* __restrict__ vinit,
                   const float* __restrict__ xinit,
                   float* __restrict__ out) {
    __shared__ float4 ring[3][QF4];        // 3 x 8KB quarter buffers
    __shared__ Aff wsum[NTHR / 32];

    const int b = blockIdx.x;
    const int l = threadIdx.x;
    const int lane = l & 31;
    const int w = l >> 5;
    const int rc = (w & 1) * 32;           // my region's chunk base in buffer

    const float4* gin  = reinterpret_cast<const float4*>(in + (long)b * T_LEN * 2);
    float4*       gout = reinterpret_cast<float4*>(out + (long)b * T_LEN);

    float vh = vinit[b], xh = xinit[b];    // state entering current half

    // ---- Prologue: each warp stages its OWN half-0 region; warps 0-1
    //      additionally prefetch their half-1 region (quarter 2). ----
    {
        int q0 = w >> 1;                   // my quarter in half 0
        float4* b0 = (w < 2) ? ring[0] : ring[1];
        stage_region(b0, gin + q0 * QF4 + rc * 8, rc, lane);
        if (w < 2)
            stage_region(ring[2], gin + 2 * QF4 + rc * 8, rc, lane);
    }

#pragma unroll
    for (int h = 0; h < 2; h++) {
        float4* X = h ? ring[2] : ring[0];   // chunks 0-63 of this half
        float4* Y = h ? ring[0] : ring[1];   // chunks 64-127
        float4* gout_h = gout + h * HO4;
        float4* mybuf = (w < 2) ? X : Y;

        // ---- Warp-local wait: only MY region must be resident ----
        if (h == 0) { if (w < 2) cp_wait<1>(); else cp_wait<0>(); }
        else        { cp_wait<0>(); }
        __syncwarp();                        // warp-scope fence for cp.async data

        const int cl   = l & 63;             // chunk within my buffer
        const int base = cl << 3;
        const int f    = Fsw(cl);

        // ---- Pass 1: compose this thread's 16-step chunk map ----
        float4 d0 = mybuf[base | (0 ^ f)];
        Aff M = step_map(d0.x, d0.y);        // identity compose peeled
        M = compose(step_map(d0.z, d0.w), M);
#pragma unroll
        for (int o = 1; o < 8; o++) {
            float4 d = mybuf[base | (o ^ f)];
            M = compose(step_map(d.x, d.y), M);
            M = compose(step_map(d.z, d.w), M);
        }

        // ---- Pass 2: warp scan of chunk maps ----
#pragma unroll
        for (int off = 1; off < 32; off <<= 1) {
            Aff o = shfl_up_aff(M, off);
            if (lane >= off) M = compose(M, o);
        }

        if (lane == 31) wsum[w] = M;
        __syncthreads();

        // ---- Cross-warp: run the carried STATE through warp-sum maps ----
        float sv = vh, sx = xh;              // running state
        float pv = vh, px = xh;              // state entering this warp
#pragma unroll
        for (int j = 0; j < NTHR / 32; j++) {
            if (j == w) { pv = sv; px = sx; }
            apply(wsum[j], sv, sx);
        }
        vh = sv; xh = sx;                    // carry: state entering next half

        // ---- Chunk-entry state via STATE shuffle ----
        float zv = pv, zx = px;
        apply(M, zv, zx);                    // state after MY chunk
        float uv = __shfl_up_sync(0xffffffffu, zv, 1);
        float ux = __shfl_up_sync(0xffffffffu, zx, 1);
        float v = (lane == 0) ? pv : uv;
        float x = (lane == 0) ? px : ux;

        // ---- Pass 3: replay 16 steps, write xddot in place ----
        // Output f4 j consumes input f4 2j,2j+1 (j <= 2j: already consumed).
#pragma unroll
        for (int j = 0; j < 4; j++) {
            float4 e0 = mybuf[base | ((2 * j) ^ f)];
            float4 e1 = mybuf[base | ((2 * j + 1) ^ f)];
            float4 o4;
            o4.x = step_state(e0.x, e0.y, v, x);
            o4.y = step_state(e0.z, e0.w, v, x);
            o4.z = step_state(e1.x, e1.y, v, x);
            o4.w = step_state(e1.z, e1.w, v, x);
            mybuf[base | (j ^ f)] = o4;
        }
        __syncthreads();                     // pass3 writes visible to drain

        // ---- Drain: swizzled smem -> coalesced streaming global store ----
#pragma unroll
        for (int r = 0; r < 4; r++) {
            int idx = r * NTHR + l;          // output f4 index in half (0..511)
            int c = idx >> 2;                // owning chunk (uniform per r-warp)
            float4* db = (c < 64) ? X : Y;
            __stcs(&gout_h[idx], db[slot(c & 63, idx & 3)]);
        }

        // ---- Warps 2-3 stage their half-1 region (Q3) into freed ring0 ----
        if (h == 0) {
            __syncthreads();                 // all drain reads done before overwrite
            if (w >= 2)
                stage_region(ring[0], gin + 3 * QF4 + rc * 8, rc, lane);
        }
    }
}

extern "C" void kernel_launch(void* const* d_in, const int* in_sizes, int n_in,
                              void* d_out, int out_size) {
    const float* in = (const float*)d_in[0];       // (B, T, 2) float32
    const float* vi = (const float*)d_in[1];       // (B, 1)
    const float* xi = (const float*)d_in[2];       // (B, 1)
    float* out = (float*)d_out;                    // (B, T, 1) float32
    const int B = in_sizes[1];                     // 4096
    spring_scan_kernel<<<B, NTHR>>>(in, vi, xi, out);
}